// round 11
// baseline (speedup 1.0000x reference)
#include <cuda_runtime.h>
#include <math.h>
#include <stdint.h>

#define NN    5000
#define EE    50000
#define LL    9
#define CC    128
#define NHEAD 8
#define NLROWS (NN*LL)   // 45000

// ------------------------- device scratch (static, no allocs) -------------------------
__device__ float g_Y[NLROWS*256];
__device__ float g_WmsgC[128*256];
__device__ float g_bz[100*128];
__device__ float g_cz[100*128];
__device__ float g_u[8*128];
__device__ float g_hidden[EE*128];
__device__ float g_rad[EE*128];
__device__ float g_msg0[(size_t)EE*128];
__device__ float g_S[(size_t)EE*72];
__device__ float g_logits[EE*8];
__device__ float g_ex[EE*8];
__device__ float g_m[NN*8];
__device__ float g_den[NN*8];
__device__ float g_outv[NN*3];
__device__ float g_outd[NN*3];
__device__ unsigned int g_maskinfo[1];

// ------------------------- helpers -------------------------
__device__ __forceinline__ float siluf(float x) { return x / (1.f + __expf(-x)); }
__device__ __forceinline__ float sigmf(float x) { return 1.f / (1.f + __expf(-x)); }

__device__ __forceinline__ void atomicMaxFloat(float* addr, float val) {
    if (val >= 0.f) atomicMax((int*)addr, __float_as_int(val));
    else            atomicMin((unsigned int*)addr, __float_as_uint(val));
}

__device__ __forceinline__ uint32_t tf32r(float x) {
    uint32_t r;
    asm("cvt.rna.tf32.f32 %0, %1;" : "=r"(r) : "f"(x));
    return r;
}

__device__ __forceinline__ void mma_tf32(float c[4], uint32_t a0, uint32_t a1, uint32_t a2, uint32_t a3,
                                         uint32_t b0, uint32_t b1) {
    asm volatile("mma.sync.aligned.m16n8k8.row.col.f32.tf32.tf32.f32 "
                 "{%0,%1,%2,%3}, {%4,%5,%6,%7}, {%8,%9}, {%0,%1,%2,%3};"
                 : "+f"(c[0]), "+f"(c[1]), "+f"(c[2]), "+f"(c[3])
                 : "r"(a0), "r"(a1), "r"(a2), "r"(a3), "r"(b0), "r"(b1));
}

// ------------------------- init / mask detect -------------------------
__global__ void k_init0() {
    int tid = blockIdx.x * blockDim.x + threadIdx.x;
    if (tid < NN*3) { g_outv[tid] = 0.f; g_outd[tid] = 0.f; }
    if (tid == 0) g_maskinfo[0] = 0u;
}

__global__ void k_detect_mask(const unsigned int* __restrict__ mask) {
    int tid = blockIdx.x * blockDim.x + threadIdx.x;
    if (tid >= NN/4) return;
    unsigned int w = mask[tid];
    if (w == 0x3F800000u)      atomicOr(g_maskinfo, 2u);
    else if (w > 1u)           atomicOr(g_maskinfo, 1u);
}

// zero m/den AND logits (logits receive atomicAdds from the alpha-GEMM epilogue)
__global__ void k_init_mden() {
    int tid = blockIdx.x * blockDim.x + threadIdx.x;
    if (tid < NN*8) { g_m[tid] = __int_as_float(0xFF800000); g_den[tid] = 0.f; }
    if (tid < EE*8) g_logits[tid] = 0.f;
}

// ------------------------- tiny precompute kernels -------------------------
__global__ void k_pack_wmsg(const float* __restrict__ Wmsg) {
    int idx = blockIdx.x * blockDim.x + threadIdx.x;
    if (idx >= 128*256) return;
    int k = idx >> 8, c = idx & 255;
    g_WmsgC[idx] = (c < 128) ? Wmsg[k*128 + c] : Wmsg[(128 + k)*128 + (c - 128)];
}

__global__ void k_zemb(const float* __restrict__ ae, const float* __restrict__ Wrad1) {
    int z = blockIdx.x;
    int c = threadIdx.x & 127;
    int half = threadIdx.x >> 7;           // 0 -> bz, 1 -> cz
    __shared__ float aes[64];
    if (threadIdx.x < 64) aes[threadIdx.x] = ae[z*64 + threadIdx.x];
    __syncthreads();
    const float* wbase = Wrad1 + (128 + half*64)*128 + c;
    float s = 0.f;
    #pragma unroll 8
    for (int k = 0; k < 64; k++) s += aes[k] * wbase[k*128];
    if (half == 0) g_bz[z*128 + c] = s;
    else           g_cz[z*128 + c] = s;
}

__global__ void k_uvec(const float* __restrict__ Wval, const float* __restrict__ Wproj) {
    int h = blockIdx.x, c = threadIdx.x;
    float s = 0.f;
    #pragma unroll
    for (int vc = 0; vc < 16; vc++)
        s += Wval[c*128 + h*16 + vc] * Wproj[h*16 + vc];
    g_u[h*128 + c] = s;
}

// ------------------------- tf32 tensor-core GEMM, pipelined, conflict-free smem -------------------------
// EPI: 0 = plain store, 1 = silu(x + bz[z_src] + cz[z_dst]) store, 2 = logits epilogue (no store)
#define PAD 8
template<int EPI>
__global__ __launch_bounds__(256, 2)
void k_gemm_tc(const float* __restrict__ A, int lda,
               const float* __restrict__ W, int ldw,
               float* __restrict__ Cout, int ldc, int M,
               const int* __restrict__ srcA, const int* __restrict__ dstA,
               const int* __restrict__ zA, const float* __restrict__ avecP)
{
    __shared__ float As[16][128 + PAD];
    __shared__ float Ws[16][128 + PAD];
    __shared__ float sAvec[128];

    const int tid  = threadIdx.x;
    const int lane = tid & 31;
    const int warp = tid >> 5;
    const int wm   = warp & 3;
    const int wn   = warp >> 2;
    const int m0   = blockIdx.x * 128;
    const int n0   = blockIdx.y * 128;

    const int g    = lane >> 2;
    const int tg   = lane & 3;

    // A-load/store mapping: conflict-free transposed scalar stores
    const int arow = tid & 127;
    const int akq  = (tid >> 7) * 8;
    const int wrow = tid >> 4;
    const int wcol = (tid & 15) * 8;

    if (EPI == 2 && tid < 128) sAvec[tid] = avecP[n0 + tid];

    const int   rowA  = m0 + arow;
    const bool  rowOK = (rowA < M);
    const float* ap = A + (size_t)rowA*lda + akq;
    const float* wp = W + (size_t)wrow*ldw + n0 + wcol;

    float acc[2][8][4];
    #pragma unroll
    for (int mi = 0; mi < 2; mi++)
        #pragma unroll
        for (int ni = 0; ni < 8; ni++)
            #pragma unroll
            for (int r = 0; r < 4; r++) acc[mi][ni][r] = 0.f;

    float4 pa0 = make_float4(0.f,0.f,0.f,0.f), pa1 = pa0;
    if (rowOK) { pa0 = *(const float4*)ap; pa1 = *(const float4*)(ap + 4); }
    float4 pw0 = *(const float4*)wp;
    float4 pw1 = *(const float4*)(wp + 4);

    for (int k0 = 0; k0 < 128; k0 += 16) {
        As[akq + 0][arow] = __uint_as_float(tf32r(pa0.x));
        As[akq + 1][arow] = __uint_as_float(tf32r(pa0.y));
        As[akq + 2][arow] = __uint_as_float(tf32r(pa0.z));
        As[akq + 3][arow] = __uint_as_float(tf32r(pa0.w));
        As[akq + 4][arow] = __uint_as_float(tf32r(pa1.x));
        As[akq + 5][arow] = __uint_as_float(tf32r(pa1.y));
        As[akq + 6][arow] = __uint_as_float(tf32r(pa1.z));
        As[akq + 7][arow] = __uint_as_float(tf32r(pa1.w));
        Ws[wrow][wcol + 0] = __uint_as_float(tf32r(pw0.x));
        Ws[wrow][wcol + 1] = __uint_as_float(tf32r(pw0.y));
        Ws[wrow][wcol + 2] = __uint_as_float(tf32r(pw0.z));
        Ws[wrow][wcol + 3] = __uint_as_float(tf32r(pw0.w));
        Ws[wrow][wcol + 4] = __uint_as_float(tf32r(pw1.x));
        Ws[wrow][wcol + 5] = __uint_as_float(tf32r(pw1.y));
        Ws[wrow][wcol + 6] = __uint_as_float(tf32r(pw1.z));
        Ws[wrow][wcol + 7] = __uint_as_float(tf32r(pw1.w));
        __syncthreads();

        if (k0 + 16 < 128) {
            if (rowOK) {
                pa0 = *(const float4*)(ap + k0 + 16);
                pa1 = *(const float4*)(ap + k0 + 20);
            }
            pw0 = *(const float4*)(wp + (size_t)(k0 + 16)*ldw);
            pw1 = *(const float4*)(wp + (size_t)(k0 + 16)*ldw + 4);
        }

        #pragma unroll
        for (int ki = 0; ki < 16; ki += 8) {
            uint32_t afrag[2][4];
            #pragma unroll
            for (int mi = 0; mi < 2; mi++) {
                int m = wm*32 + mi*16 + g;
                afrag[mi][0] = __float_as_uint(As[ki + tg    ][m    ]);
                afrag[mi][1] = __float_as_uint(As[ki + tg    ][m + 8]);
                afrag[mi][2] = __float_as_uint(As[ki + tg + 4][m    ]);
                afrag[mi][3] = __float_as_uint(As[ki + tg + 4][m + 8]);
            }
            #pragma unroll
            for (int ni = 0; ni < 8; ni++) {
                int n = wn*64 + ni*8 + g;
                uint32_t b0 = __float_as_uint(Ws[ki + tg    ][n]);
                uint32_t b1 = __float_as_uint(Ws[ki + tg + 4][n]);
                mma_tf32(acc[0][ni], afrag[0][0], afrag[0][1], afrag[0][2], afrag[0][3], b0, b1);
                mma_tf32(acc[1][ni], afrag[1][0], afrag[1][1], afrag[1][2], afrag[1][3], b0, b1);
            }
        }
        __syncthreads();
    }

    if (EPI == 2) {
        // logits epilogue: logits[row][h] = sum_col LR(a)*avec[col]; no C store
        const int hb = n0 >> 5;
        #pragma unroll
        for (int mi = 0; mi < 2; mi++) {
            #pragma unroll
            for (int r = 0; r < 2; r++) {
                int row = m0 + wm*32 + mi*16 + g + r*8;
                float s0 = 0.f, s1 = 0.f;
                #pragma unroll
                for (int ni = 0; ni < 8; ni++) {
                    int lcol = wn*64 + ni*8 + 2*tg;
                    float c0 = acc[mi][ni][r*2 + 0];
                    float c1 = acc[mi][ni][r*2 + 1];
                    float t0 = (c0 > 0.f ? c0 : 0.2f*c0) * sAvec[lcol];
                    float t1 = (c1 > 0.f ? c1 : 0.2f*c1) * sAvec[lcol + 1];
                    if (ni < 4) s0 += t0 + t1; else s1 += t0 + t1;
                }
                s0 += __shfl_xor_sync(0xffffffffu, s0, 1);
                s0 += __shfl_xor_sync(0xffffffffu, s0, 2);
                s1 += __shfl_xor_sync(0xffffffffu, s1, 1);
                s1 += __shfl_xor_sync(0xffffffffu, s1, 2);
                if (tg == 0 && row < M) {
                    atomicAdd(&g_logits[(size_t)row*8 + hb + wn*2 + 0], s0);
                    atomicAdd(&g_logits[(size_t)row*8 + hb + wn*2 + 1], s1);
                }
            }
        }
        return;
    }

    #pragma unroll
    for (int mi = 0; mi < 2; mi++) {
        #pragma unroll
        for (int r = 0; r < 2; r++) {
            int row = m0 + wm*32 + mi*16 + g + r*8;
            if (row >= M) continue;
            int colbase = n0 + wn*64 + 2*tg;
            if (EPI == 1) {
                int zs = zA[srcA[row]], zd = zA[dstA[row]];
                #pragma unroll
                for (int ni = 0; ni < 8; ni++) {
                    int col = colbase + ni*8;
                    float c0 = acc[mi][ni][r*2 + 0];
                    float c1 = acc[mi][ni][r*2 + 1];
                    c0 = siluf(c0 + g_bz[zs*128 + col]     + g_cz[zd*128 + col]);
                    c1 = siluf(c1 + g_bz[zs*128 + col + 1] + g_cz[zd*128 + col + 1]);
                    *(float2*)(Cout + (size_t)row*ldc + col) = make_float2(c0, c1);
                }
            } else {
                #pragma unroll
                for (int ni = 0; ni < 8; ni++) {
                    int col = colbase + ni*8;
                    *(float2*)(Cout + (size_t)row*ldc + col) =
                        make_float2(acc[mi][ni][r*2 + 0], acc[mi][ni][r*2 + 1]);
                }
            }
        }
    }
}

// ------------------------- pass 1: msg0 + S[e,j,h] -------------------------
__global__ __launch_bounds__(256)
void k_fuse1(const float* __restrict__ wigner,
             const int* __restrict__ src, const int* __restrict__ dst)
{
    __shared__ float4 us[8][32];
    const int tid  = threadIdx.x;
    const int warp = tid >> 5, lane = tid & 31;

    us[tid >> 5][tid & 31] = ((const float4*)g_u)[tid];
    __syncthreads();

    const int e = blockIdx.x * 8 + warp;
    if (e >= EE) return;

    float w0 = (lane < 9) ? wigner[(size_t)e*81 + lane] : 0.f;
    const int s = src[e], d = dst[e];
    const float4* Ys = (const float4*)g_Y + (size_t)s*9*64 + lane;
    const float4* Yd = (const float4*)g_Y + (size_t)d*9*64 + 32 + lane;

    float4 t[9];
    #pragma unroll
    for (int j = 0; j < 9; j++) {
        float4 a = Ys[j*64], b = Yd[j*64];
        t[j] = make_float4(a.x + b.x, a.y + b.y, a.z + b.z, a.w + b.w);
    }

    float4 r4 = ((const float4*)g_rad)[(size_t)e*32 + lane];

    float4 m0 = make_float4(0.f, 0.f, 0.f, 0.f);
    #pragma unroll
    for (int j = 0; j < 9; j++) {
        float w = __shfl_sync(0xffffffffu, w0, j);
        m0.x += w*t[j].x; m0.y += w*t[j].y; m0.z += w*t[j].z; m0.w += w*t[j].w;
    }
    m0.x *= r4.x; m0.y *= r4.y; m0.z *= r4.z; m0.w *= r4.w;
    ((float4*)g_msg0)[(size_t)e*32 + lane] = m0;

    float4 z = make_float4(sigmf(m0.x)*r4.x, sigmf(m0.y)*r4.y, sigmf(m0.z)*r4.z, sigmf(m0.w)*r4.w);

    const int myh = (lane >> 2) & 7;
    #pragma unroll
    for (int j = 0; j < 9; j++) {
        float4 tz = make_float4(t[j].x*z.x, t[j].y*z.y, t[j].z*z.z, t[j].w*z.w);
        float p[8];
        #pragma unroll
        for (int h = 0; h < 8; h++) {
            float4 uu = us[h][lane];
            p[h] = tz.x*uu.x + tz.y*uu.y + tz.z*uu.z + tz.w*uu.w;
        }
        {
            bool up = (lane & 16);
            float q[4];
            #pragma unroll
            for (int i = 0; i < 4; i++) {
                float got = __shfl_xor_sync(0xffffffffu, p[(up ? 0 : 4) + i], 16);
                q[i] = p[(up ? 4 : 0) + i] + got;
            }
            bool up8 = (lane & 8);
            float q2[2];
            #pragma unroll
            for (int i = 0; i < 2; i++) {
                float got = __shfl_xor_sync(0xffffffffu, q[(up8 ? 0 : 2) + i], 8);
                q2[i] = q[(up8 ? 2 : 0) + i] + got;
            }
            bool up4 = (lane & 4);
            float got = __shfl_xor_sync(0xffffffffu, q2[up4 ? 0 : 1], 4);
            float v = q2[up4 ? 1 : 0] + got;
            v += __shfl_xor_sync(0xffffffffu, v, 1);
            v += __shfl_xor_sync(0xffffffffu, v, 2);
            if ((lane & 3) == 0)
                g_S[(size_t)e*72 + j*8 + myh] = v;
        }
    }
}

// ------------------------- segment max over completed logits -------------------------
__global__ void k_seg_max(const int* __restrict__ dst)
{
    int tid = blockIdx.x * blockDim.x + threadIdx.x;
    if (tid >= EE*8) return;
    int e = tid >> 3, h = tid & 7;
    atomicMaxFloat(&g_m[dst[e]*8 + h], g_logits[tid]);
}

__global__ void k_expsum(const int* __restrict__ dst)
{
    int tid = blockIdx.x * blockDim.x + threadIdx.x;
    if (tid >= EE*8) return;
    int e = tid >> 3, h = tid & 7;
    int d = dst[e];
    float ex = __expf(g_logits[tid] - g_m[d*8 + h]);
    g_ex[tid] = ex;
    atomicAdd(&g_den[d*8 + h], ex);
}

// ------------------------- pass 2: attn -> R_j -> wigner gram -> scatter -------------------------
__global__ __launch_bounds__(256)
void k_edge_out2(const float* __restrict__ wigner,
                 const int* __restrict__ dst, float* __restrict__ outp)
{
    const int warp = threadIdx.x >> 5, lane = threadIdx.x & 31;
    const int e = blockIdx.x * 8 + warp;
    if (e >= EE) return;
    const int d = dst[e];

    float attn = 0.f;
    if (lane < 8) attn = g_ex[(size_t)e*8 + lane] / (g_den[d*8 + lane] + 1e-9f);

    float R = 0.f;
    {
        const float* Sp = g_S + (size_t)e*72 + lane*8;
        #pragma unroll
        for (int h = 0; h < 8; h++) {
            float ah = __shfl_sync(0xffffffffu, attn, h);
            float sv = 0.f;
            if (lane < 9) sv = Sp[h];
            R += ah * sv;
        }
    }

    float c = 0.f;
    {
        const float* wl = wigner + (size_t)e*81 + lane*9;
        #pragma unroll
        for (int j = 0; j < 9; j++) {
            float Rj = __shfl_sync(0xffffffffu, R, j);
            if (lane < 9) c += wl[j] * Rj;
        }
    }

    float o = 0.f;
    {
        #pragma unroll
        for (int l = 0; l < 9; l++) {
            float cl = __shfl_sync(0xffffffffu, c, l);
            if (lane < 3) o += wigner[(size_t)e*81 + l*9 + (lane + 1)] * cl;
        }
    }
    if (lane < 3) atomicAdd(&outp[d*3 + lane], o);
}

// ------------------------- final select -------------------------
__global__ void k_final(const unsigned char* __restrict__ mask, float* __restrict__ out)
{
    int tid = blockIdx.x * blockDim.x + threadIdx.x;
    if (tid >= NN*3) return;
    int n = tid / 3;
    unsigned int info = g_maskinfo[0];
    bool mk;
    if (info & 2u)      mk = (((const float*)mask)[n] != 0.f);
    else if (info & 1u) mk = (mask[n] != 0);
    else                mk = (((const int*)mask)[n] != 0);
    out[tid] = mk ? g_outd[tid] : g_outv[tid];
}

// ------------------------- host launch -------------------------
extern "C" void kernel_launch(void* const* d_in, const int* in_sizes, int n_in,
                              void* d_out, int out_size)
{
    float *pY, *pWmsgC, *pHidden, *pRad, *pMsg0, *pOutv, *pOutd;
    cudaGetSymbolAddress((void**)&pY, g_Y);
    cudaGetSymbolAddress((void**)&pWmsgC, g_WmsgC);
    cudaGetSymbolAddress((void**)&pHidden, g_hidden);
    cudaGetSymbolAddress((void**)&pRad, g_rad);
    cudaGetSymbolAddress((void**)&pMsg0, g_msg0);
    cudaGetSymbolAddress((void**)&pOutv, g_outv);
    cudaGetSymbolAddress((void**)&pOutd, g_outd);

    const float* node_emb  = (const float*)d_in[0];
    const float* edge_dist = (const float*)d_in[1];
    const float* wigner    = (const float*)d_in[2];
    const int *atomic_numbers, *edge_index;
    const void* mask;
    int pbase[2];
    bool dictOrder = (in_sizes[3] == NN);
    if (dictOrder) {
        atomic_numbers = (const int*)d_in[3];
        edge_index     = (const int*)d_in[4];
        mask           = d_in[5];
        pbase[0] = 6; pbase[1] = 14;
    } else {
        pbase[0] = 3; pbase[1] = 11;
        atomic_numbers = (const int*)d_in[19];
        edge_index     = (const int*)d_in[20];
        mask           = d_in[21];
    }
    const int* src = edge_index;
    const int* dst = edge_index + EE;

    k_init0<<<(NN*3 + 255)/256, 256>>>();
    k_detect_mask<<<(NN/4 + 255)/256, 256>>>((const unsigned int*)mask);

    for (int t = 0; t < 2; t++) {
        int b = pbase[t];
        const float* ae     = (const float*)d_in[b + 0];
        const float* Wrad1  = (const float*)d_in[b + 1];
        const float* Wrad2  = (const float*)d_in[b + 2];
        const float* Wmsg   = (const float*)d_in[b + 3];
        const float* Walpha = (const float*)d_in[b + 4];
        const float* avec   = (const float*)d_in[b + 5];
        const float* Wval   = (const float*)d_in[b + 6];
        const float* Wproj  = (const float*)d_in[b + 7];

        k_pack_wmsg<<<128, 256>>>(Wmsg);
        // Y GEMM at global launch #4 so the ncu window samples it (A/B vs R9 profile)
        k_gemm_tc<0><<<dim3((NLROWS + 127)/128, 2), 256>>>(node_emb, 128, pWmsgC, 256, pY, 256, NLROWS,
                                                           nullptr, nullptr, nullptr, nullptr);
        k_zemb<<<100, 256>>>(ae, Wrad1);
        k_uvec<<<8, 128>>>(Wval, Wproj);

        k_gemm_tc<1><<<dim3((EE + 127)/128, 1), 256>>>(edge_dist, 128, Wrad1, 128, pHidden, 128, EE,
                                                       src, dst, atomic_numbers, nullptr);
        k_gemm_tc<0><<<dim3((EE + 127)/128, 1), 256>>>(pHidden, 128, Wrad2, 128, pRad, 128, EE,
                                                       nullptr, nullptr, nullptr, nullptr);
        k_fuse1<<<(EE + 7)/8, 256>>>(wigner, src, dst);
        // zero m/den/logits BEFORE the alpha GEMM (its epilogue atomically accumulates logits)
        k_init_mden<<<(EE*8 + 255)/256, 256>>>();
        // alpha GEMM with fused logits epilogue (no abuf materialization)
        k_gemm_tc<2><<<dim3((EE + 127)/128, 2), 256>>>(pMsg0, 128, Walpha, 256, nullptr, 0, EE,
                                                       nullptr, nullptr, nullptr, avec);
        k_seg_max<<<(EE*8 + 255)/256, 256>>>(dst);
        k_expsum<<<(EE*8 + 255)/256, 256>>>(dst);
        k_edge_out2<<<(EE + 7)/8, 256>>>(wigner, dst, (t == 0) ? pOutv : pOutd);
    }

    k_final<<<(NN*3 + 255)/256, 256>>>((const unsigned char*)mask, (float*)d_out);
}

// round 13
// speedup vs baseline: 1.0624x; 1.0624x over previous
#include <cuda_runtime.h>
#include <math.h>
#include <stdint.h>

#define NN    5000
#define EE    50000
#define LL    9
#define CC    128
#define NHEAD 8
#define NLROWS (NN*LL)   // 45000

// ------------------------- device scratch (static, no allocs) -------------------------
__device__ float g_Y[NLROWS*256];
__device__ float g_WmsgC[128*256];
__device__ float g_bz[100*128];
__device__ float g_cz[100*128];
__device__ float g_u[8*128];
__device__ float g_hidden[EE*128];
__device__ float g_rad[EE*128];
__device__ float g_msg0[(size_t)EE*128];
__device__ float g_S[(size_t)EE*72];
__device__ float g_logits[EE*8];
__device__ float g_ex[EE*8];
__device__ float g_m[NN*8];
__device__ float g_den[NN*8];
__device__ float g_outv[NN*3];
__device__ float g_outd[NN*3];
__device__ unsigned int g_maskinfo[1];

// ------------------------- helpers -------------------------
__device__ __forceinline__ float siluf(float x) { return x / (1.f + __expf(-x)); }
__device__ __forceinline__ float sigmf(float x) { return 1.f / (1.f + __expf(-x)); }

__device__ __forceinline__ void atomicMaxFloat(float* addr, float val) {
    if (val >= 0.f) atomicMax((int*)addr, __float_as_int(val));
    else            atomicMin((unsigned int*)addr, __float_as_uint(val));
}

__device__ __forceinline__ uint32_t tf32r(float x) {
    uint32_t r;
    asm("cvt.rna.tf32.f32 %0, %1;" : "=r"(r) : "f"(x));
    return r;
}

__device__ __forceinline__ void mma_tf32(float c[4], uint32_t a0, uint32_t a1, uint32_t a2, uint32_t a3,
                                         uint32_t b0, uint32_t b1) {
    asm volatile("mma.sync.aligned.m16n8k8.row.col.f32.tf32.tf32.f32 "
                 "{%0,%1,%2,%3}, {%4,%5,%6,%7}, {%8,%9}, {%0,%1,%2,%3};"
                 : "+f"(c[0]), "+f"(c[1]), "+f"(c[2]), "+f"(c[3])
                 : "r"(a0), "r"(a1), "r"(a2), "r"(a3), "r"(b0), "r"(b1));
}

// ------------------------- merged init + mask detect -------------------------
__global__ void k_init_all(const unsigned int* __restrict__ mask) {
    int tid = blockIdx.x * blockDim.x + threadIdx.x;
    if (tid < NN*3) { g_outv[tid] = 0.f; g_outd[tid] = 0.f; }
    if (tid == 0) g_maskinfo[0] = 0u;
    if (tid < NN/4) {
        unsigned int w = mask[tid];
        if (w == 0x3F800000u)      atomicOr(g_maskinfo, 2u);
        else if (w > 1u)           atomicOr(g_maskinfo, 1u);
    }
}

// ------------------------- merged per-tag preprocessing -------------------------
// blocks [0,128)    : pack Wmsg -> g_WmsgC          (256 thr)
// blocks [128,228)  : zemb (bz/cz for z=blk-128)    (256 thr)
// blocks [228,236)  : uvec (h=blk-228)              (128 of 256 thr)
// blocks [236,1799) : init m/den/logits             (256 thr)
#define PRE_BLOCKS 1799
__global__ void k_pre(const float* __restrict__ Wmsg,
                      const float* __restrict__ ae, const float* __restrict__ Wrad1,
                      const float* __restrict__ Wval, const float* __restrict__ Wproj)
{
    const int blk = blockIdx.x;
    const int t   = threadIdx.x;
    if (blk < 128) {
        int idx = blk*256 + t;          // < 32768 = 128*256
        int k = idx >> 8, c = idx & 255;
        g_WmsgC[idx] = (c < 128) ? Wmsg[k*128 + c] : Wmsg[(128 + k)*128 + (c - 128)];
    } else if (blk < 228) {
        int z = blk - 128;
        int c = t & 127;
        int half = t >> 7;
        __shared__ float aes[64];
        if (t < 64) aes[t] = ae[z*64 + t];
        __syncthreads();
        const float* wbase = Wrad1 + (128 + half*64)*128 + c;
        float s = 0.f;
        #pragma unroll 8
        for (int k = 0; k < 64; k++) s += aes[k] * wbase[k*128];
        if (half == 0) g_bz[z*128 + c] = s;
        else           g_cz[z*128 + c] = s;
    } else if (blk < 236) {
        if (t < 128) {
            int h = blk - 228, c = t;
            float s = 0.f;
            #pragma unroll
            for (int vc = 0; vc < 16; vc++)
                s += Wval[c*128 + h*16 + vc] * Wproj[h*16 + vc];
            g_u[h*128 + c] = s;
        }
    } else {
        int base = (blk - 236)*256 + t;
        if (base < NN*8) { g_m[base] = __int_as_float(0xFF800000); g_den[base] = 0.f; }
        if (base < EE*8) g_logits[base] = 0.f;
    }
}

// ------------------------- tf32 tensor-core GEMM, double-buffered smem -------------------------
// EPI: 0 = plain store, 1 = silu(x + bz[z_src] + cz[z_dst]) store, 2 = logits epilogue (no store)
#define PAD 8
template<int EPI>
__global__ __launch_bounds__(256, 2)
void k_gemm_tc(const float* __restrict__ A, int lda,
               const float* __restrict__ W, int ldw,
               float* __restrict__ Cout, int ldc, int M,
               const int* __restrict__ srcA, const int* __restrict__ dstA,
               const int* __restrict__ zA, const float* __restrict__ avecP)
{
    __shared__ float As[2][16][128 + PAD];
    __shared__ float Ws[2][16][128 + PAD];
    __shared__ float sAvec[128];

    const int tid  = threadIdx.x;
    const int lane = tid & 31;
    const int warp = tid >> 5;
    const int wm   = warp & 3;
    const int wn   = warp >> 2;
    const int m0   = blockIdx.x * 128;
    const int n0   = blockIdx.y * 128;

    const int g    = lane >> 2;
    const int tg   = lane & 3;

    const int arow = tid & 127;
    const int akq  = (tid >> 7) * 8;
    const int wrow = tid >> 4;
    const int wcol = (tid & 15) * 8;

    if (EPI == 2 && tid < 128) sAvec[tid] = avecP[n0 + tid];

    const int   rowA  = m0 + arow;
    const bool  rowOK = (rowA < M);
    const float* ap = A + (size_t)rowA*lda + akq;
    const float* wp = W + (size_t)wrow*ldw + n0 + wcol;

    float acc[2][8][4];
    #pragma unroll
    for (int mi = 0; mi < 2; mi++)
        #pragma unroll
        for (int ni = 0; ni < 8; ni++)
            #pragma unroll
            for (int r = 0; r < 4; r++) acc[mi][ni][r] = 0.f;

    // stage k0=0 into buffer 0
    float4 pa0 = make_float4(0.f,0.f,0.f,0.f), pa1 = pa0;
    if (rowOK) { pa0 = *(const float4*)ap; pa1 = *(const float4*)(ap + 4); }
    float4 pw0 = *(const float4*)wp;
    float4 pw1 = *(const float4*)(wp + 4);
    {
        float (*Ab)[128 + PAD] = As[0];
        float (*Wb)[128 + PAD] = Ws[0];
        Ab[akq + 0][arow] = __uint_as_float(tf32r(pa0.x));
        Ab[akq + 1][arow] = __uint_as_float(tf32r(pa0.y));
        Ab[akq + 2][arow] = __uint_as_float(tf32r(pa0.z));
        Ab[akq + 3][arow] = __uint_as_float(tf32r(pa0.w));
        Ab[akq + 4][arow] = __uint_as_float(tf32r(pa1.x));
        Ab[akq + 5][arow] = __uint_as_float(tf32r(pa1.y));
        Ab[akq + 6][arow] = __uint_as_float(tf32r(pa1.z));
        Ab[akq + 7][arow] = __uint_as_float(tf32r(pa1.w));
        Wb[wrow][wcol + 0] = __uint_as_float(tf32r(pw0.x));
        Wb[wrow][wcol + 1] = __uint_as_float(tf32r(pw0.y));
        Wb[wrow][wcol + 2] = __uint_as_float(tf32r(pw0.z));
        Wb[wrow][wcol + 3] = __uint_as_float(tf32r(pw0.w));
        Wb[wrow][wcol + 4] = __uint_as_float(tf32r(pw1.x));
        Wb[wrow][wcol + 5] = __uint_as_float(tf32r(pw1.y));
        Wb[wrow][wcol + 6] = __uint_as_float(tf32r(pw1.z));
        Wb[wrow][wcol + 7] = __uint_as_float(tf32r(pw1.w));
    }

    int buf = 0;
    for (int k0 = 0; k0 < 128; k0 += 16) {
        const bool more = (k0 + 16 < 128);
        if (more) {
            if (rowOK) {
                pa0 = *(const float4*)(ap + k0 + 16);
                pa1 = *(const float4*)(ap + k0 + 20);
            }
            pw0 = *(const float4*)(wp + (size_t)(k0 + 16)*ldw);
            pw1 = *(const float4*)(wp + (size_t)(k0 + 16)*ldw + 4);
        }
        __syncthreads();   // buf ready for readers; prior readers of buf^1 done
        if (more) {
            float (*Ab)[128 + PAD] = As[buf ^ 1];
            float (*Wb)[128 + PAD] = Ws[buf ^ 1];
            Ab[akq + 0][arow] = __uint_as_float(tf32r(pa0.x));
            Ab[akq + 1][arow] = __uint_as_float(tf32r(pa0.y));
            Ab[akq + 2][arow] = __uint_as_float(tf32r(pa0.z));
            Ab[akq + 3][arow] = __uint_as_float(tf32r(pa0.w));
            Ab[akq + 4][arow] = __uint_as_float(tf32r(pa1.x));
            Ab[akq + 5][arow] = __uint_as_float(tf32r(pa1.y));
            Ab[akq + 6][arow] = __uint_as_float(tf32r(pa1.z));
            Ab[akq + 7][arow] = __uint_as_float(tf32r(pa1.w));
            Wb[wrow][wcol + 0] = __uint_as_float(tf32r(pw0.x));
            Wb[wrow][wcol + 1] = __uint_as_float(tf32r(pw0.y));
            Wb[wrow][wcol + 2] = __uint_as_float(tf32r(pw0.z));
            Wb[wrow][wcol + 3] = __uint_as_float(tf32r(pw0.w));
            Wb[wrow][wcol + 4] = __uint_as_float(tf32r(pw1.x));
            Wb[wrow][wcol + 5] = __uint_as_float(tf32r(pw1.y));
            Wb[wrow][wcol + 6] = __uint_as_float(tf32r(pw1.z));
            Wb[wrow][wcol + 7] = __uint_as_float(tf32r(pw1.w));
        }

        float (*Ar)[128 + PAD] = As[buf];
        float (*Wr)[128 + PAD] = Ws[buf];
        #pragma unroll
        for (int ki = 0; ki < 16; ki += 8) {
            uint32_t afrag[2][4];
            #pragma unroll
            for (int mi = 0; mi < 2; mi++) {
                int m = wm*32 + mi*16 + g;
                afrag[mi][0] = __float_as_uint(Ar[ki + tg    ][m    ]);
                afrag[mi][1] = __float_as_uint(Ar[ki + tg    ][m + 8]);
                afrag[mi][2] = __float_as_uint(Ar[ki + tg + 4][m    ]);
                afrag[mi][3] = __float_as_uint(Ar[ki + tg + 4][m + 8]);
            }
            #pragma unroll
            for (int ni = 0; ni < 8; ni++) {
                int n = wn*64 + ni*8 + g;
                uint32_t b0 = __float_as_uint(Wr[ki + tg    ][n]);
                uint32_t b1 = __float_as_uint(Wr[ki + tg + 4][n]);
                mma_tf32(acc[0][ni], afrag[0][0], afrag[0][1], afrag[0][2], afrag[0][3], b0, b1);
                mma_tf32(acc[1][ni], afrag[1][0], afrag[1][1], afrag[1][2], afrag[1][3], b0, b1);
            }
        }
        buf ^= 1;
    }

    if (EPI == 2) {
        const int hb = n0 >> 5;
        #pragma unroll
        for (int mi = 0; mi < 2; mi++) {
            #pragma unroll
            for (int r = 0; r < 2; r++) {
                int row = m0 + wm*32 + mi*16 + g + r*8;
                float s0 = 0.f, s1 = 0.f;
                #pragma unroll
                for (int ni = 0; ni < 8; ni++) {
                    int lcol = wn*64 + ni*8 + 2*tg;
                    float c0 = acc[mi][ni][r*2 + 0];
                    float c1 = acc[mi][ni][r*2 + 1];
                    float t0 = (c0 > 0.f ? c0 : 0.2f*c0) * sAvec[lcol];
                    float t1 = (c1 > 0.f ? c1 : 0.2f*c1) * sAvec[lcol + 1];
                    if (ni < 4) s0 += t0 + t1; else s1 += t0 + t1;
                }
                s0 += __shfl_xor_sync(0xffffffffu, s0, 1);
                s0 += __shfl_xor_sync(0xffffffffu, s0, 2);
                s1 += __shfl_xor_sync(0xffffffffu, s1, 1);
                s1 += __shfl_xor_sync(0xffffffffu, s1, 2);
                if (tg == 0 && row < M) {
                    atomicAdd(&g_logits[(size_t)row*8 + hb + wn*2 + 0], s0);
                    atomicAdd(&g_logits[(size_t)row*8 + hb + wn*2 + 1], s1);
                }
            }
        }
        return;
    }

    #pragma unroll
    for (int mi = 0; mi < 2; mi++) {
        #pragma unroll
        for (int r = 0; r < 2; r++) {
            int row = m0 + wm*32 + mi*16 + g + r*8;
            if (row >= M) continue;
            int colbase = n0 + wn*64 + 2*tg;
            if (EPI == 1) {
                int zs = zA[srcA[row]], zd = zA[dstA[row]];
                #pragma unroll
                for (int ni = 0; ni < 8; ni++) {
                    int col = colbase + ni*8;
                    float c0 = acc[mi][ni][r*2 + 0];
                    float c1 = acc[mi][ni][r*2 + 1];
                    c0 = siluf(c0 + g_bz[zs*128 + col]     + g_cz[zd*128 + col]);
                    c1 = siluf(c1 + g_bz[zs*128 + col + 1] + g_cz[zd*128 + col + 1]);
                    *(float2*)(Cout + (size_t)row*ldc + col) = make_float2(c0, c1);
                }
            } else {
                #pragma unroll
                for (int ni = 0; ni < 8; ni++) {
                    int col = colbase + ni*8;
                    *(float2*)(Cout + (size_t)row*ldc + col) =
                        make_float2(acc[mi][ni][r*2 + 0], acc[mi][ni][r*2 + 1]);
                }
            }
        }
    }
}

// ------------------------- pass 1: msg0 + S[e,j,h] -------------------------
__global__ __launch_bounds__(256)
void k_fuse1(const float* __restrict__ wigner,
             const int* __restrict__ src, const int* __restrict__ dst)
{
    __shared__ float4 us[8][32];
    const int tid  = threadIdx.x;
    const int warp = tid >> 5, lane = tid & 31;

    us[tid >> 5][tid & 31] = ((const float4*)g_u)[tid];
    __syncthreads();

    const int e = blockIdx.x * 8 + warp;
    if (e >= EE) return;

    float w0 = (lane < 9) ? wigner[(size_t)e*81 + lane] : 0.f;
    const int s = src[e], d = dst[e];
    const float4* Ys = (const float4*)g_Y + (size_t)s*9*64 + lane;
    const float4* Yd = (const float4*)g_Y + (size_t)d*9*64 + 32 + lane;

    float4 t[9];
    #pragma unroll
    for (int j = 0; j < 9; j++) {
        float4 a = Ys[j*64], b = Yd[j*64];
        t[j] = make_float4(a.x + b.x, a.y + b.y, a.z + b.z, a.w + b.w);
    }

    float4 r4 = ((const float4*)g_rad)[(size_t)e*32 + lane];

    float4 m0 = make_float4(0.f, 0.f, 0.f, 0.f);
    #pragma unroll
    for (int j = 0; j < 9; j++) {
        float w = __shfl_sync(0xffffffffu, w0, j);
        m0.x += w*t[j].x; m0.y += w*t[j].y; m0.z += w*t[j].z; m0.w += w*t[j].w;
    }
    m0.x *= r4.x; m0.y *= r4.y; m0.z *= r4.z; m0.w *= r4.w;
    ((float4*)g_msg0)[(size_t)e*32 + lane] = m0;

    float4 z = make_float4(sigmf(m0.x)*r4.x, sigmf(m0.y)*r4.y, sigmf(m0.z)*r4.z, sigmf(m0.w)*r4.w);

    const int myh = (lane >> 2) & 7;
    #pragma unroll
    for (int j = 0; j < 9; j++) {
        float4 tz = make_float4(t[j].x*z.x, t[j].y*z.y, t[j].z*z.z, t[j].w*z.w);
        float p[8];
        #pragma unroll
        for (int h = 0; h < 8; h++) {
            float4 uu = us[h][lane];
            p[h] = tz.x*uu.x + tz.y*uu.y + tz.z*uu.z + tz.w*uu.w;
        }
        {
            bool up = (lane & 16);
            float q[4];
            #pragma unroll
            for (int i = 0; i < 4; i++) {
                float got = __shfl_xor_sync(0xffffffffu, p[(up ? 0 : 4) + i], 16);
                q[i] = p[(up ? 4 : 0) + i] + got;
            }
            bool up8 = (lane & 8);
            float q2[2];
            #pragma unroll
            for (int i = 0; i < 2; i++) {
                float got = __shfl_xor_sync(0xffffffffu, q[(up8 ? 0 : 2) + i], 8);
                q2[i] = q[(up8 ? 2 : 0) + i] + got;
            }
            bool up4 = (lane & 4);
            float got = __shfl_xor_sync(0xffffffffu, q2[up4 ? 0 : 1], 4);
            float v = q2[up4 ? 1 : 0] + got;
            v += __shfl_xor_sync(0xffffffffu, v, 1);
            v += __shfl_xor_sync(0xffffffffu, v, 2);
            if ((lane & 3) == 0)
                g_S[(size_t)e*72 + j*8 + myh] = v;
        }
    }
}

// ------------------------- segment max / expsum -------------------------
__global__ void k_seg_max(const int* __restrict__ dst)
{
    int tid = blockIdx.x * blockDim.x + threadIdx.x;
    if (tid >= EE*8) return;
    int e = tid >> 3, h = tid & 7;
    atomicMaxFloat(&g_m[dst[e]*8 + h], g_logits[tid]);
}

__global__ void k_expsum(const int* __restrict__ dst)
{
    int tid = blockIdx.x * blockDim.x + threadIdx.x;
    if (tid >= EE*8) return;
    int e = tid >> 3, h = tid & 7;
    int d = dst[e];
    float ex = __expf(g_logits[tid] - g_m[d*8 + h]);
    g_ex[tid] = ex;
    atomicAdd(&g_den[d*8 + h], ex);
}

// ------------------------- pass 2: attn -> R_j -> wigner gram -> scatter -------------------------
__global__ __launch_bounds__(256)
void k_edge_out2(const float* __restrict__ wigner,
                 const int* __restrict__ dst, float* __restrict__ outp)
{
    const int warp = threadIdx.x >> 5, lane = threadIdx.x & 31;
    const int e = blockIdx.x * 8 + warp;
    if (e >= EE) return;
    const int d = dst[e];

    float attn = 0.f;
    if (lane < 8) attn = g_ex[(size_t)e*8 + lane] / (g_den[d*8 + lane] + 1e-9f);

    float R = 0.f;
    {
        const float* Sp = g_S + (size_t)e*72 + lane*8;
        #pragma unroll
        for (int h = 0; h < 8; h++) {
            float ah = __shfl_sync(0xffffffffu, attn, h);
            float sv = 0.f;
            if (lane < 9) sv = Sp[h];
            R += ah * sv;
        }
    }

    float c = 0.f;
    {
        const float* wl = wigner + (size_t)e*81 + lane*9;
        #pragma unroll
        for (int j = 0; j < 9; j++) {
            float Rj = __shfl_sync(0xffffffffu, R, j);
            if (lane < 9) c += wl[j] * Rj;
        }
    }

    float o = 0.f;
    {
        #pragma unroll
        for (int l = 0; l < 9; l++) {
            float cl = __shfl_sync(0xffffffffu, c, l);
            if (lane < 3) o += wigner[(size_t)e*81 + l*9 + (lane + 1)] * cl;
        }
    }
    if (lane < 3) atomicAdd(&outp[d*3 + lane], o);
}

// ------------------------- final select -------------------------
__global__ void k_final(const unsigned char* __restrict__ mask, float* __restrict__ out)
{
    int tid = blockIdx.x * blockDim.x + threadIdx.x;
    if (tid >= NN*3) return;
    int n = tid / 3;
    unsigned int info = g_maskinfo[0];
    bool mk;
    if (info & 2u)      mk = (((const float*)mask)[n] != 0.f);
    else if (info & 1u) mk = (mask[n] != 0);
    else                mk = (((const int*)mask)[n] != 0);
    out[tid] = mk ? g_outd[tid] : g_outv[tid];
}

// ------------------------- host launch -------------------------
extern "C" void kernel_launch(void* const* d_in, const int* in_sizes, int n_in,
                              void* d_out, int out_size)
{
    float *pY, *pWmsgC, *pHidden, *pRad, *pMsg0, *pOutv, *pOutd;
    cudaGetSymbolAddress((void**)&pY, g_Y);
    cudaGetSymbolAddress((void**)&pWmsgC, g_WmsgC);
    cudaGetSymbolAddress((void**)&pHidden, g_hidden);
    cudaGetSymbolAddress((void**)&pRad, g_rad);
    cudaGetSymbolAddress((void**)&pMsg0, g_msg0);
    cudaGetSymbolAddress((void**)&pOutv, g_outv);
    cudaGetSymbolAddress((void**)&pOutd, g_outd);

    const float* node_emb  = (const float*)d_in[0];
    const float* edge_dist = (const float*)d_in[1];
    const float* wigner    = (const float*)d_in[2];
    const int *atomic_numbers, *edge_index;
    const void* mask;
    int pbase[2];
    bool dictOrder = (in_sizes[3] == NN);
    if (dictOrder) {
        atomic_numbers = (const int*)d_in[3];
        edge_index     = (const int*)d_in[4];
        mask           = d_in[5];
        pbase[0] = 6; pbase[1] = 14;
    } else {
        pbase[0] = 3; pbase[1] = 11;
        atomic_numbers = (const int*)d_in[19];
        edge_index     = (const int*)d_in[20];
        mask           = d_in[21];
    }
    const int* src = edge_index;
    const int* dst = edge_index + EE;

    k_init_all<<<(NN*3 + 255)/256, 256>>>((const unsigned int*)mask);

    for (int t = 0; t < 2; t++) {
        int b = pbase[t];
        const float* ae     = (const float*)d_in[b + 0];
        const float* Wrad1  = (const float*)d_in[b + 1];
        const float* Wrad2  = (const float*)d_in[b + 2];
        const float* Wmsg   = (const float*)d_in[b + 3];
        const float* Walpha = (const float*)d_in[b + 4];
        const float* avec   = (const float*)d_in[b + 5];
        const float* Wval   = (const float*)d_in[b + 6];
        const float* Wproj  = (const float*)d_in[b + 7];

        // merged preprocessing: pack + zemb + uvec + init m/den/logits
        k_pre<<<PRE_BLOCKS, 256>>>(Wmsg, ae, Wrad1, Wval, Wproj);
        // Y = node_embedding @ [Wm_top | Wm_bot]
        k_gemm_tc<0><<<dim3((NLROWS + 127)/128, 2), 256>>>(node_emb, 128, pWmsgC, 256, pY, 256, NLROWS,
                                                           nullptr, nullptr, nullptr, nullptr);
        // hidden = silu(dist @ W1a + bz + cz)   (4th launch on tag 0 -> ncu sample)
        k_gemm_tc<1><<<dim3((EE + 127)/128, 1), 256>>>(edge_dist, 128, Wrad1, 128, pHidden, 128, EE,
                                                       src, dst, atomic_numbers, nullptr);
        // rad = hidden @ W_rad2
        k_gemm_tc<0><<<dim3((EE + 127)/128, 1), 256>>>(pHidden, 128, Wrad2, 128, pRad, 128, EE,
                                                       nullptr, nullptr, nullptr, nullptr);
        // fused msg0 + S
        k_fuse1<<<(EE + 7)/8, 256>>>(wigner, src, dst);
        // alpha GEMM with fused logits epilogue
        k_gemm_tc<2><<<dim3((EE + 127)/128, 2), 256>>>(pMsg0, 128, Walpha, 256, nullptr, 0, EE,
                                                       nullptr, nullptr, nullptr, avec);
        k_seg_max<<<(EE*8 + 255)/256, 256>>>(dst);
        k_expsum<<<(EE*8 + 255)/256, 256>>>(dst);
        k_edge_out2<<<(EE + 7)/8, 256>>>(wigner, dst, (t == 0) ? pOutv : pOutd);
    }

    k_final<<<(NN*3 + 255)/256, 256>>>((const unsigned char*)mask, (float*)d_out);
}